// round 15
// baseline (speedup 1.0000x reference)
#include <cuda_runtime.h>
#include <cuda_fp16.h>
#include <cstdint>
#include <math.h>

// ===========================================================================
// Problem constants
// ===========================================================================
constexpr int Bc = 2;
constexpr int Sc = 2048;
constexpr int Ec = 1024;
constexpr int Hc = 16;
constexpr int HDc = 64;
constexpr int Mc = Bc * Sc;        // 4096
constexpr int E3 = 3 * Ec;         // 3072

// Scratch (no cudaMalloc allowed)
__device__ __half g_x16[Mc * Ec];
__device__ __half g_wq16[E3 * Ec];
__device__ __half g_wo16[Ec * Ec];
__device__ __half g_qkv16[Mc * E3];
__device__ __half g_attn16[Mc * Ec];

// scores computed in log2 domain; scale folded into Q at QKV epilogue
constexpr float SCALE_LOG2E = 0.125f * 1.4426950408889634f;

// ===========================================================================
// Helpers
// ===========================================================================
__device__ __forceinline__ uint32_t pack_f2(float a, float b) {
    __half2 t = __float22half2_rn(make_float2(a, b));
    return *reinterpret_cast<uint32_t*>(&t);
}
__device__ __forceinline__ uint32_t smem_u32(const void* p) {
    return (uint32_t)__cvta_generic_to_shared(p);
}
__device__ __forceinline__ void ldm_x4(uint32_t addr, uint32_t r[4]) {
    asm volatile("ldmatrix.sync.aligned.m8n8.x4.shared.b16 {%0,%1,%2,%3}, [%4];"
        : "=r"(r[0]), "=r"(r[1]), "=r"(r[2]), "=r"(r[3]) : "r"(addr));
}
__device__ __forceinline__ void ldm_x4_t(uint32_t addr, uint32_t r[4]) {
    asm volatile("ldmatrix.sync.aligned.m8n8.x4.trans.shared.b16 {%0,%1,%2,%3}, [%4];"
        : "=r"(r[0]), "=r"(r[1]), "=r"(r[2]), "=r"(r[3]) : "r"(addr));
}
__device__ __forceinline__ void mma_f16(float c[4], const uint32_t a[4],
                                        uint32_t b0, uint32_t b1) {
    asm volatile(
        "mma.sync.aligned.m16n8k16.row.col.f32.f16.f16.f32 "
        "{%0,%1,%2,%3}, {%4,%5,%6,%7}, {%8,%9}, {%0,%1,%2,%3};"
        : "+f"(c[0]), "+f"(c[1]), "+f"(c[2]), "+f"(c[3])
        : "r"(a[0]), "r"(a[1]), "r"(a[2]), "r"(a[3]), "r"(b0), "r"(b1));
}
#define CP16(dst, src) \
    asm volatile("cp.async.cg.shared.global [%0], [%1], 16;" :: "r"(dst), "l"(src))
#define CP_COMMIT() asm volatile("cp.async.commit_group;")
#define CP_WAIT0()  asm volatile("cp.async.wait_group 0;")
#define CP_WAIT1()  asm volatile("cp.async.wait_group 1;")

// ===========================================================================
// Prepass: round x, qkv_w, out_w fp32 -> fp16 in ONE kernel
// ===========================================================================
constexpr int NX4  = Mc * Ec / 4;
constexpr int NWQ4 = E3 * Ec / 4;
constexpr int NWO4 = Ec * Ec / 4;
constexpr int NALL4 = NX4 + NWQ4 + NWO4;

__global__ void round_all_kernel(const float* __restrict__ x,
                                 const float* __restrict__ wq,
                                 const float* __restrict__ wo,
                                 __half* __restrict__ x16,
                                 __half* __restrict__ wq16,
                                 __half* __restrict__ wo16)
{
    int i = blockIdx.x * blockDim.x + threadIdx.x;
    if (i >= NALL4) return;
    const float* src; __half* dst; int j;
    if (i < NX4)             { src = x;  dst = x16;  j = i; }
    else if (i < NX4 + NWQ4) { src = wq; dst = wq16; j = i - NX4; }
    else                     { src = wo; dst = wo16; j = i - NX4 - NWQ4; }
    float4 v = reinterpret_cast<const float4*>(src)[j];
    reinterpret_cast<uint2*>(dst)[j] = make_uint2(pack_f2(v.x, v.y), pack_f2(v.z, v.w));
}

// ===========================================================================
// fp16 GEMM: CTA 128x128, 8 warps (2M x 4N), warp tile 64x32.
// K-chunk 64, 3-stage cp.async pipeline, LDT=72 (conflict-free).
// HALF_OUT: fp16 C; q columns (col < Ec) pre-scaled by SCALE_LOG2E.
// ===========================================================================
constexpr int LDT = 72;
constexpr int TEL = 128 * LDT;               // 9216 elems per tile
constexpr int STAGE = 2 * TEL;               // A+B = 18432 elems
constexpr int GEMM_SMEM = 3 * STAGE * 2;     // 110592 B

template<bool HALF_OUT>
__global__ __launch_bounds__(256, 2)
void gemm_f16_kernel(const __half* __restrict__ Ag, const __half* __restrict__ Bg,
                     const float* __restrict__ bias,
                     float* __restrict__ C, __half* __restrict__ Ch,
                     int M, int N, int K)
{
    extern __shared__ __half sm[];

    int tid  = threadIdx.x;
    int lane = tid & 31;
    int wid  = tid >> 5;
    int wm   = wid >> 2;
    int wn   = wid & 3;
    int bm   = blockIdx.y * 128;
    int bn   = blockIdx.x * 128;

    int lrow  = lane & 15;
    int lhalf = (lane >> 4) * 8;

    int r0  = tid >> 2;            // 0..63
    int seg = (tid & 3) * 16;      // 0,16,32,48 (halves)

    const __half* gsA = Ag + (size_t)bm * K;
    const __half* gsB = Bg + (size_t)bn * K;

    auto load_stage = [&](int stg, int k0) {
        __half* st = sm + stg * STAGE;
        #pragma unroll
        for (int i = 0; i < 2; i++) {
            int row = r0 + 64 * i;
            const __half* ga = gsA + (size_t)row * K + k0 + seg;
            const __half* gb = gsB + (size_t)row * K + k0 + seg;
            uint32_t sa = smem_u32(st + row * LDT + seg);
            uint32_t sb = smem_u32(st + TEL + row * LDT + seg);
            CP16(sa,      ga);
            CP16(sa + 16, ga + 8);
            CP16(sb,      gb);
            CP16(sb + 16, gb + 8);
        }
    };

    float acc[4][4][4] = {};

    load_stage(0, 0);  CP_COMMIT();
    load_stage(1, 64); CP_COMMIT();

    const int nch = K / 64;   // 16
    int slot = 0;
    for (int c = 0; c < nch; c++) {
        CP_WAIT1();
        __syncthreads();

        if (c + 2 < nch) load_stage((c + 2) % 3, (c + 2) * 64);
        CP_COMMIT();

        __half* A = sm + slot * STAGE;
        __half* B = A + TEL;
        slot = (slot == 2) ? 0 : slot + 1;

        #pragma unroll
        for (int ks = 0; ks < 4; ks++) {
            int kk = ks * 16 + lhalf;

            uint32_t af[4][4];
            uint32_t bf[2][4];
            #pragma unroll
            for (int mt = 0; mt < 4; mt++)
                ldm_x4(smem_u32(A + (wm * 64 + mt * 16 + lrow) * LDT + kk), af[mt]);
            #pragma unroll
            for (int nt = 0; nt < 2; nt++)
                ldm_x4(smem_u32(B + (wn * 32 + nt * 16 + lrow) * LDT + kk), bf[nt]);

            #pragma unroll
            for (int mt = 0; mt < 4; mt++)
                #pragma unroll
                for (int nt = 0; nt < 2; nt++) {
                    mma_f16(acc[mt][nt*2+0], af[mt], bf[nt][0], bf[nt][2]);
                    mma_f16(acc[mt][nt*2+1], af[mt], bf[nt][1], bf[nt][3]);
                }
        }
    }

    // ---- epilogue ----
    #pragma unroll
    for (int mt = 0; mt < 4; mt++) {
        int row = bm + wm * 64 + mt * 16 + (lane >> 2);
        #pragma unroll
        for (int n8 = 0; n8 < 4; n8++) {
            int col = bn + wn * 32 + n8 * 8 + (lane & 3) * 2;
            float2 bb = *reinterpret_cast<const float2*>(bias + col);
            float v0 = acc[mt][n8][0] + bb.x, v1 = acc[mt][n8][1] + bb.y;
            float v2 = acc[mt][n8][2] + bb.x, v3 = acc[mt][n8][3] + bb.y;
            if (HALF_OUT) {
                float qs = (col < Ec) ? SCALE_LOG2E : 1.0f;
                v0 *= qs; v1 *= qs; v2 *= qs; v3 *= qs;
                *reinterpret_cast<uint32_t*>(Ch + (size_t)row * N + col)       = pack_f2(v0, v1);
                *reinterpret_cast<uint32_t*>(Ch + (size_t)(row + 8) * N + col) = pack_f2(v2, v3);
            } else {
                *reinterpret_cast<float2*>(C + (size_t)row * N + col)       = make_float2(v0, v1);
                *reinterpret_cast<float2*>(C + (size_t)(row + 8) * N + col) = make_float2(v2, v3);
            }
        }
    }
}

// ===========================================================================
// Flash attention (causal), tensor cores, plain fp16.
// 256 q-rows per CTA, 512 threads (16 warps x 16 rows) — halves KV traffic.
// Q pre-scaled (log2 domain); fine-grained causal skip; 3-stage KV pipeline.
// ===========================================================================
constexpr int QROWS = 256;
constexpr int LDH = 72;
constexpr int FQ  = QROWS * LDH;             // 18432
constexpr int FKV = 64 * LDH;                // 4608
constexpr int KVSTAGE = 2 * FKV;             // Kh, Vh = 9216
constexpr int FLASH_ELEMS = FQ + 3 * KVSTAGE;       // 46080
constexpr int FLASH_SMEM  = FLASH_ELEMS * 2;        // 92160 B

__global__ __launch_bounds__(512, 1)
void flash_tc_kernel(const __half* __restrict__ qkv)
{
    extern __shared__ __half fs[];
    __half* Qh = fs;
    __half* KV = fs + FQ;

    int tid  = threadIdx.x;
    int lane = tid & 31;
    int wq   = tid >> 5;                      // 0..15
    int qt   = gridDim.x - 1 - blockIdx.x;    // heavy q-tiles first
    int h    = blockIdx.y;
    int b    = blockIdx.z;
    int q0   = qt * QROWS;

    int lrow = lane & 15;
    int lh8  = (lane >> 4) * 8;
    int warp_row_lo = q0 + wq * 16;

    // ---- Q tile loads (256 rows x 8 chunks = 2048; 512 thr x 4) ----
    {
        #pragma unroll
        for (int i = 0; i < 4; i++) {
            int s   = tid + 512 * i;
            int row = s >> 3;
            int ch  = (s & 7) * 8;
            CP16(smem_u32(Qh + row * LDH + ch),
                 qkv + (size_t)(b * Sc + q0 + row) * E3 + h * HDc + ch);
        }
    }

    auto load_kv = [&](int stg, int kc0) {
        __half* st = KV + stg * KVSTAGE;
        // 64 rows x 8 chunks = 512; one per thread
        int row = tid >> 3;
        int ch  = (tid & 7) * 8;
        size_t gk = (size_t)(b * Sc + kc0 + row) * E3 + Ec + h * HDc + ch;
        uint32_t so = row * LDH + ch;
        CP16(smem_u32(st + so),       qkv + gk);
        CP16(smem_u32(st + FKV + so), qkv + gk + Ec);
    };

    const int nkt = 4 * qt + 4;
    load_kv(0, 0);  CP_COMMIT();   // group: Q + KV0
    load_kv(1, 64); CP_COMMIT();

    float o[8][4] = {};
    float mrow[2] = {-1e30f, -1e30f};
    float lsum[2] = {0.f, 0.f};

    // Q fragments loop-invariant: hoist after first wait
    uint32_t aqf[4][4];
    bool qloaded = false;

    int slot = 0;
    for (int kt = 0; kt < nkt; kt++) {
        int kc0 = kt * 64;
        CP_WAIT1();
        __syncthreads();

        if (kt + 2 < nkt) load_kv((kt + 2) % 3, (kt + 2) * 64);
        CP_COMMIT();

        __half* Kh = KV + slot * KVSTAGE;
        __half* Vh = Kh + FKV;
        slot = (slot == 2) ? 0 : slot + 1;

        if (kc0 <= warp_row_lo + 15) {
            if (!qloaded) {
                #pragma unroll
                for (int ksj = 0; ksj < 4; ksj++)
                    ldm_x4(smem_u32(Qh + (wq * 16 + lrow) * LDH + ksj * 16 + lh8), aqf[ksj]);
                qloaded = true;
            }
            bool domask = (kc0 + 63 > warp_row_lo);
            int dnt  = (warp_row_lo - kc0) >> 4;
            int nlim = domask ? dnt + 1 : 4;

            // ---- S = Q K^T (1-pass; skip fully-masked subtiles) ----
            float s[8][4] = {};
            #pragma unroll
            for (int ksj = 0; ksj < 4; ksj++) {
                int kk = ksj * 16 + lh8;
                #pragma unroll
                for (int nt = 0; nt < 4; nt++) {
                    if (nt < nlim) {
                        uint32_t kh[4];
                        ldm_x4(smem_u32(Kh + (nt * 16 + lrow) * LDH + kk), kh);
                        mma_f16(s[2*nt+0], aqf[ksj], kh[0], kh[2]);
                        mma_f16(s[2*nt+1], aqf[ksj], kh[1], kh[3]);
                    }
                }
            }

            // ---- mask (scale already folded into Q) ----
            if (domask) {
                int r_lo = warp_row_lo + (lane >> 2);
                #pragma unroll
                for (int n8 = 0; n8 < 8; n8++) {
                    #pragma unroll
                    for (int cc = 0; cc < 4; cc++) {
                        float v = s[n8][cc];
                        if ((n8 >> 1) > dnt) {
                            v = -1e30f;
                        } else if ((n8 >> 1) == dnt) {
                            int col = kc0 + n8 * 8 + (lane & 3) * 2 + (cc & 1);
                            int row = r_lo + (cc >> 1) * 8;
                            if (col > row) v = -1e30f;
                        }
                        s[n8][cc] = v;
                    }
                }
            }

            // ---- online softmax (exp2 domain) ----
            #pragma unroll
            for (int hh = 0; hh < 2; hh++) {
                float tm = -1e30f;
                #pragma unroll
                for (int n8 = 0; n8 < 8; n8++)
                    tm = fmaxf(tm, fmaxf(s[n8][2*hh], s[n8][2*hh+1]));
                tm = fmaxf(tm, __shfl_xor_sync(0xffffffffu, tm, 1));
                tm = fmaxf(tm, __shfl_xor_sync(0xffffffffu, tm, 2));
                float mn = fmaxf(mrow[hh], tm);
                float corr = exp2f(mrow[hh] - mn);
                mrow[hh] = mn;
                float rs = 0.f;
                #pragma unroll
                for (int n8 = 0; n8 < 8; n8++) {
                    s[n8][2*hh]   = exp2f(s[n8][2*hh]   - mn);
                    s[n8][2*hh+1] = exp2f(s[n8][2*hh+1] - mn);
                    rs += s[n8][2*hh] + s[n8][2*hh+1];
                }
                rs += __shfl_xor_sync(0xffffffffu, rs, 1);
                rs += __shfl_xor_sync(0xffffffffu, rs, 2);
                lsum[hh] = lsum[hh] * corr + rs;
                #pragma unroll
                for (int n8 = 0; n8 < 8; n8++) {
                    o[n8][2*hh]   *= corr;
                    o[n8][2*hh+1] *= corr;
                }
            }

            // ---- O += P V (1-pass; skip zero key-subtiles — exact) ----
            #pragma unroll
            for (int j = 0; j < 4; j++) {
                if (j < nlim) {
                    uint32_t pA[4];
                    #pragma unroll
                    for (int q2 = 0; q2 < 2; q2++) {
                        const float* sp = s[2*j + q2];
                        pA[q2*2 + 0] = pack_f2(sp[0], sp[1]);
                        pA[q2*2 + 1] = pack_f2(sp[2], sp[3]);
                    }
                    #pragma unroll
                    for (int nt = 0; nt < 4; nt++) {
                        uint32_t vh[4];
                        ldm_x4_t(smem_u32(Vh + (j * 16 + lrow) * LDH + nt * 16 + lh8), vh);
                        mma_f16(o[2*nt+0], pA, vh[0], vh[1]);
                        mma_f16(o[2*nt+1], pA, vh[2], vh[3]);
                    }
                }
            }
        }
    }

    // ---- epilogue: normalize, round, write fp16 attn ----
    #pragma unroll
    for (int hh = 0; hh < 2; hh++) {
        float inv = 1.0f / lsum[hh];
        int row = warp_row_lo + (lane >> 2) + hh * 8;
        size_t base = (size_t)(b * Sc + row) * Ec + h * HDc;
        #pragma unroll
        for (int n8 = 0; n8 < 8; n8++) {
            int d = n8 * 8 + (lane & 3) * 2;
            *reinterpret_cast<uint32_t*>(g_attn16 + base + d) =
                pack_f2(o[n8][2*hh] * inv, o[n8][2*hh+1] * inv);
        }
    }
}

// ===========================================================================
extern "C" void kernel_launch(void* const* d_in, const int* in_sizes, int n_in,
                              void* d_out, int out_size)
{
    const float* x      = (const float*)d_in[0];
    const float* qkv_w  = (const float*)d_in[1];
    const float* qkv_b  = (const float*)d_in[2];
    const float* out_w  = (const float*)d_in[3];
    const float* out_b  = (const float*)d_in[4];
    float* out = (float*)d_out;

    __half *x16, *wq16, *wo16, *qkv16, *a16;
    cudaGetSymbolAddress((void**)&x16,   g_x16);
    cudaGetSymbolAddress((void**)&wq16,  g_wq16);
    cudaGetSymbolAddress((void**)&wo16,  g_wo16);
    cudaGetSymbolAddress((void**)&qkv16, g_qkv16);
    cudaGetSymbolAddress((void**)&a16,   g_attn16);

    cudaFuncSetAttribute(gemm_f16_kernel<true>,
                         cudaFuncAttributeMaxDynamicSharedMemorySize, GEMM_SMEM);
    cudaFuncSetAttribute(gemm_f16_kernel<false>,
                         cudaFuncAttributeMaxDynamicSharedMemorySize, GEMM_SMEM);
    cudaFuncSetAttribute(flash_tc_kernel,
                         cudaFuncAttributeMaxDynamicSharedMemorySize, FLASH_SMEM);

    // 0) prepass
    round_all_kernel<<<(NALL4 + 255) / 256, 256>>>(x, qkv_w, out_w, x16, wq16, wo16);

    // 1) QKV projection -> fp16 qkv (q columns pre-scaled)
    dim3 g1(E3 / 128, Mc / 128);   // (24, 32)
    gemm_f16_kernel<true><<<g1, 256, GEMM_SMEM>>>(x16, wq16, qkv_b, nullptr, qkv16, Mc, E3, Ec);

    // 2) Flash attention -> fp16 attn (256-row q-tiles, 512 threads)
    dim3 g2(Sc / QROWS, Hc, Bc);   // (8, 16, 2)
    flash_tc_kernel<<<g2, 512, FLASH_SMEM>>>(qkv16);

    // 3) Output projection -> fp32 out
    dim3 g3(Ec / 128, Mc / 128);   // (8, 32)
    gemm_f16_kernel<false><<<g3, 256, GEMM_SMEM>>>(a16, wo16, out_b, out, nullptr, Mc, Ec, Ec);
}

// round 16
// speedup vs baseline: 1.0560x; 1.0560x over previous
#include <cuda_runtime.h>
#include <cuda_fp16.h>
#include <cstdint>
#include <math.h>

// ===========================================================================
// Problem constants
// ===========================================================================
constexpr int Bc = 2;
constexpr int Sc = 2048;
constexpr int Ec = 1024;
constexpr int Hc = 16;
constexpr int HDc = 64;
constexpr int Mc = Bc * Sc;        // 4096
constexpr int E3 = 3 * Ec;         // 3072

// Scratch (no cudaMalloc allowed)
__device__ __half g_x16[Mc * Ec];
__device__ __half g_wq16[E3 * Ec];
__device__ __half g_wo16[Ec * Ec];
__device__ __half g_qkv16[Mc * E3];
__device__ __half g_attn16[Mc * Ec];

// scores computed in log2 domain; scale folded into Q at QKV epilogue
constexpr float SCALE_LOG2E = 0.125f * 1.4426950408889634f;

// ===========================================================================
// Helpers
// ===========================================================================
__device__ __forceinline__ uint32_t pack_f2(float a, float b) {
    __half2 t = __float22half2_rn(make_float2(a, b));
    return *reinterpret_cast<uint32_t*>(&t);
}
__device__ __forceinline__ uint32_t smem_u32(const void* p) {
    return (uint32_t)__cvta_generic_to_shared(p);
}
__device__ __forceinline__ void ldm_x4(uint32_t addr, uint32_t r[4]) {
    asm volatile("ldmatrix.sync.aligned.m8n8.x4.shared.b16 {%0,%1,%2,%3}, [%4];"
        : "=r"(r[0]), "=r"(r[1]), "=r"(r[2]), "=r"(r[3]) : "r"(addr));
}
__device__ __forceinline__ void ldm_x4_t(uint32_t addr, uint32_t r[4]) {
    asm volatile("ldmatrix.sync.aligned.m8n8.x4.trans.shared.b16 {%0,%1,%2,%3}, [%4];"
        : "=r"(r[0]), "=r"(r[1]), "=r"(r[2]), "=r"(r[3]) : "r"(addr));
}
__device__ __forceinline__ void mma_f16(float c[4], const uint32_t a[4],
                                        uint32_t b0, uint32_t b1) {
    asm volatile(
        "mma.sync.aligned.m16n8k16.row.col.f32.f16.f16.f32 "
        "{%0,%1,%2,%3}, {%4,%5,%6,%7}, {%8,%9}, {%0,%1,%2,%3};"
        : "+f"(c[0]), "+f"(c[1]), "+f"(c[2]), "+f"(c[3])
        : "r"(a[0]), "r"(a[1]), "r"(a[2]), "r"(a[3]), "r"(b0), "r"(b1));
}
#define CP16(dst, src) \
    asm volatile("cp.async.cg.shared.global [%0], [%1], 16;" :: "r"(dst), "l"(src))
#define CP_COMMIT() asm volatile("cp.async.commit_group;")
#define CP_WAIT0()  asm volatile("cp.async.wait_group 0;")
#define CP_WAIT1()  asm volatile("cp.async.wait_group 1;")
#define CP_WAIT2()  asm volatile("cp.async.wait_group 2;")

// ===========================================================================
// Prepass: round x, qkv_w, out_w fp32 -> fp16 in ONE kernel
// ===========================================================================
constexpr int NX4  = Mc * Ec / 4;
constexpr int NWQ4 = E3 * Ec / 4;
constexpr int NWO4 = Ec * Ec / 4;
constexpr int NALL4 = NX4 + NWQ4 + NWO4;

__global__ void round_all_kernel(const float* __restrict__ x,
                                 const float* __restrict__ wq,
                                 const float* __restrict__ wo,
                                 __half* __restrict__ x16,
                                 __half* __restrict__ wq16,
                                 __half* __restrict__ wo16)
{
    int i = blockIdx.x * blockDim.x + threadIdx.x;
    if (i >= NALL4) return;
    const float* src; __half* dst; int j;
    if (i < NX4)             { src = x;  dst = x16;  j = i; }
    else if (i < NX4 + NWQ4) { src = wq; dst = wq16; j = i - NX4; }
    else                     { src = wo; dst = wo16; j = i - NX4 - NWQ4; }
    float4 v = reinterpret_cast<const float4*>(src)[j];
    reinterpret_cast<uint2*>(dst)[j] = make_uint2(pack_f2(v.x, v.y), pack_f2(v.z, v.w));
}

// ===========================================================================
// fp16 GEMM: CTA 128x128, 8 warps (2M x 4N), warp tile 64x32.
// K-chunk 64, 3-stage cp.async pipeline, LDT=72 (conflict-free).
// HALF_OUT: fp16 C; q columns (col < Ec) pre-scaled by SCALE_LOG2E.
// ===========================================================================
constexpr int LDT = 72;
constexpr int TEL = 128 * LDT;               // 9216 elems per tile
constexpr int STAGE = 2 * TEL;               // A+B = 18432 elems
constexpr int GEMM_SMEM = 3 * STAGE * 2;     // 110592 B

template<bool HALF_OUT>
__global__ __launch_bounds__(256, 2)
void gemm_f16_kernel(const __half* __restrict__ Ag, const __half* __restrict__ Bg,
                     const float* __restrict__ bias,
                     float* __restrict__ C, __half* __restrict__ Ch,
                     int M, int N, int K)
{
    extern __shared__ __half sm[];

    int tid  = threadIdx.x;
    int lane = tid & 31;
    int wid  = tid >> 5;
    int wm   = wid >> 2;
    int wn   = wid & 3;
    int bm   = blockIdx.y * 128;
    int bn   = blockIdx.x * 128;

    int lrow  = lane & 15;
    int lhalf = (lane >> 4) * 8;

    int r0  = tid >> 2;            // 0..63
    int seg = (tid & 3) * 16;      // 0,16,32,48 (halves)

    const __half* gsA = Ag + (size_t)bm * K;
    const __half* gsB = Bg + (size_t)bn * K;

    auto load_stage = [&](int stg, int k0) {
        __half* st = sm + stg * STAGE;
        #pragma unroll
        for (int i = 0; i < 2; i++) {
            int row = r0 + 64 * i;
            const __half* ga = gsA + (size_t)row * K + k0 + seg;
            const __half* gb = gsB + (size_t)row * K + k0 + seg;
            uint32_t sa = smem_u32(st + row * LDT + seg);
            uint32_t sb = smem_u32(st + TEL + row * LDT + seg);
            CP16(sa,      ga);
            CP16(sa + 16, ga + 8);
            CP16(sb,      gb);
            CP16(sb + 16, gb + 8);
        }
    };

    float acc[4][4][4] = {};

    load_stage(0, 0);  CP_COMMIT();
    load_stage(1, 64); CP_COMMIT();

    const int nch = K / 64;   // 16
    int slot = 0;
    for (int c = 0; c < nch; c++) {
        CP_WAIT1();
        __syncthreads();

        if (c + 2 < nch) load_stage((c + 2) % 3, (c + 2) * 64);
        CP_COMMIT();

        __half* A = sm + slot * STAGE;
        __half* B = A + TEL;
        slot = (slot == 2) ? 0 : slot + 1;

        #pragma unroll
        for (int ks = 0; ks < 4; ks++) {
            int kk = ks * 16 + lhalf;

            uint32_t af[4][4];
            uint32_t bf[2][4];
            #pragma unroll
            for (int mt = 0; mt < 4; mt++)
                ldm_x4(smem_u32(A + (wm * 64 + mt * 16 + lrow) * LDT + kk), af[mt]);
            #pragma unroll
            for (int nt = 0; nt < 2; nt++)
                ldm_x4(smem_u32(B + (wn * 32 + nt * 16 + lrow) * LDT + kk), bf[nt]);

            #pragma unroll
            for (int mt = 0; mt < 4; mt++)
                #pragma unroll
                for (int nt = 0; nt < 2; nt++) {
                    mma_f16(acc[mt][nt*2+0], af[mt], bf[nt][0], bf[nt][2]);
                    mma_f16(acc[mt][nt*2+1], af[mt], bf[nt][1], bf[nt][3]);
                }
        }
    }

    // ---- epilogue ----
    #pragma unroll
    for (int mt = 0; mt < 4; mt++) {
        int row = bm + wm * 64 + mt * 16 + (lane >> 2);
        #pragma unroll
        for (int n8 = 0; n8 < 4; n8++) {
            int col = bn + wn * 32 + n8 * 8 + (lane & 3) * 2;
            float2 bb = *reinterpret_cast<const float2*>(bias + col);
            float v0 = acc[mt][n8][0] + bb.x, v1 = acc[mt][n8][1] + bb.y;
            float v2 = acc[mt][n8][2] + bb.x, v3 = acc[mt][n8][3] + bb.y;
            if (HALF_OUT) {
                float qs = (col < Ec) ? SCALE_LOG2E : 1.0f;
                v0 *= qs; v1 *= qs; v2 *= qs; v3 *= qs;
                *reinterpret_cast<uint32_t*>(Ch + (size_t)row * N + col)       = pack_f2(v0, v1);
                *reinterpret_cast<uint32_t*>(Ch + (size_t)(row + 8) * N + col) = pack_f2(v2, v3);
            } else {
                *reinterpret_cast<float2*>(C + (size_t)row * N + col)       = make_float2(v0, v1);
                *reinterpret_cast<float2*>(C + (size_t)(row + 8) * N + col) = make_float2(v2, v3);
            }
        }
    }
}

// ===========================================================================
// Flash attention (causal), tensor cores, plain fp16. R14 config:
// 128 q-rows, 256 threads (8 warps x 16 rows), 2 CTAs/SM.
// 4-stage KV cp.async pipeline (deeper prefetch). Fine-grained causal skip.
// ===========================================================================
constexpr int LDH = 72;
constexpr int FQ  = 128 * LDH;               // 9216
constexpr int FKV = 64 * LDH;                // 4608
constexpr int KVSTAGE = 2 * FKV;             // Kh, Vh = 9216
constexpr int NSTG = 4;
constexpr int FLASH_ELEMS = FQ + NSTG * KVSTAGE;    // 46080
constexpr int FLASH_SMEM  = FLASH_ELEMS * 2;        // 92160 B

__global__ __launch_bounds__(256, 2)
void flash_tc_kernel(const __half* __restrict__ qkv)
{
    extern __shared__ __half fs[];
    __half* Qh = fs;
    __half* KV = fs + FQ;

    int tid  = threadIdx.x;
    int lane = tid & 31;
    int wq   = tid >> 5;
    int qt   = gridDim.x - 1 - blockIdx.x;    // heavy q-tiles first
    int h    = blockIdx.y;
    int b    = blockIdx.z;
    int q0   = qt * 128;

    int lrow = lane & 15;
    int lh8  = (lane >> 4) * 8;
    int warp_row_lo = q0 + wq * 16;

    {
        #pragma unroll
        for (int i = 0; i < 4; i++) {
            int s   = tid + 256 * i;
            int row = s >> 3;
            int ch  = (s & 7) * 8;
            CP16(smem_u32(Qh + row * LDH + ch),
                 qkv + (size_t)(b * Sc + q0 + row) * E3 + h * HDc + ch);
        }
    }

    auto load_kv = [&](int stg, int kc0) {
        __half* st = KV + stg * KVSTAGE;
        #pragma unroll
        for (int i = 0; i < 2; i++) {
            int s   = tid + 256 * i;
            int row = s >> 3;
            int ch  = (s & 7) * 8;
            size_t gk = (size_t)(b * Sc + kc0 + row) * E3 + Ec + h * HDc + ch;
            uint32_t so = row * LDH + ch;
            CP16(smem_u32(st + so),       qkv + gk);
            CP16(smem_u32(st + FKV + so), qkv + gk + Ec);
        }
    };

    const int nkt = 2 * qt + 2;
    load_kv(0, 0);   CP_COMMIT();    // group: Q + KV0
    load_kv(1, 64);  CP_COMMIT();    // nkt >= 2 always
    if (2 < nkt) load_kv(2, 128);
    CP_COMMIT();                     // (possibly empty) group keeps invariant

    float o[8][4] = {};
    float mrow[2] = {-1e30f, -1e30f};
    float lsum[2] = {0.f, 0.f};

    uint32_t aqf[4][4];
    bool qloaded = false;

    int slot = 0;
    for (int kt = 0; kt < nkt; kt++) {
        int kc0 = kt * 64;
        CP_WAIT2();        // stage kt resident (2 younger groups may be in flight)
        __syncthreads();

        if (kt + 3 < nkt) load_kv((kt + 3) % NSTG, (kt + 3) * 64);
        CP_COMMIT();

        __half* Kh = KV + slot * KVSTAGE;
        __half* Vh = Kh + FKV;
        slot = (slot == NSTG - 1) ? 0 : slot + 1;

        if (kc0 <= warp_row_lo + 15) {
            if (!qloaded) {
                #pragma unroll
                for (int ksj = 0; ksj < 4; ksj++)
                    ldm_x4(smem_u32(Qh + (wq * 16 + lrow) * LDH + ksj * 16 + lh8), aqf[ksj]);
                qloaded = true;
            }
            bool domask = (kc0 + 63 > warp_row_lo);
            int dnt  = (warp_row_lo - kc0) >> 4;
            int nlim = domask ? dnt + 1 : 4;

            // ---- S = Q K^T (1-pass; skip fully-masked subtiles) ----
            float s[8][4] = {};
            #pragma unroll
            for (int ksj = 0; ksj < 4; ksj++) {
                int kk = ksj * 16 + lh8;
                #pragma unroll
                for (int nt = 0; nt < 4; nt++) {
                    if (nt < nlim) {
                        uint32_t kh[4];
                        ldm_x4(smem_u32(Kh + (nt * 16 + lrow) * LDH + kk), kh);
                        mma_f16(s[2*nt+0], aqf[ksj], kh[0], kh[2]);
                        mma_f16(s[2*nt+1], aqf[ksj], kh[1], kh[3]);
                    }
                }
            }

            // ---- mask (scale already folded into Q) ----
            if (domask) {
                int r_lo = warp_row_lo + (lane >> 2);
                #pragma unroll
                for (int n8 = 0; n8 < 8; n8++) {
                    #pragma unroll
                    for (int cc = 0; cc < 4; cc++) {
                        float v = s[n8][cc];
                        if ((n8 >> 1) > dnt) {
                            v = -1e30f;
                        } else if ((n8 >> 1) == dnt) {
                            int col = kc0 + n8 * 8 + (lane & 3) * 2 + (cc & 1);
                            int row = r_lo + (cc >> 1) * 8;
                            if (col > row) v = -1e30f;
                        }
                        s[n8][cc] = v;
                    }
                }
            }

            // ---- online softmax (exp2 domain) ----
            #pragma unroll
            for (int hh = 0; hh < 2; hh++) {
                float tm = -1e30f;
                #pragma unroll
                for (int n8 = 0; n8 < 8; n8++)
                    tm = fmaxf(tm, fmaxf(s[n8][2*hh], s[n8][2*hh+1]));
                tm = fmaxf(tm, __shfl_xor_sync(0xffffffffu, tm, 1));
                tm = fmaxf(tm, __shfl_xor_sync(0xffffffffu, tm, 2));
                float mn = fmaxf(mrow[hh], tm);
                float corr = exp2f(mrow[hh] - mn);
                mrow[hh] = mn;
                float rs = 0.f;
                #pragma unroll
                for (int n8 = 0; n8 < 8; n8++) {
                    s[n8][2*hh]   = exp2f(s[n8][2*hh]   - mn);
                    s[n8][2*hh+1] = exp2f(s[n8][2*hh+1] - mn);
                    rs += s[n8][2*hh] + s[n8][2*hh+1];
                }
                rs += __shfl_xor_sync(0xffffffffu, rs, 1);
                rs += __shfl_xor_sync(0xffffffffu, rs, 2);
                lsum[hh] = lsum[hh] * corr + rs;
                #pragma unroll
                for (int n8 = 0; n8 < 8; n8++) {
                    o[n8][2*hh]   *= corr;
                    o[n8][2*hh+1] *= corr;
                }
            }

            // ---- O += P V (1-pass; skip zero key-subtiles — exact) ----
            #pragma unroll
            for (int j = 0; j < 4; j++) {
                if (j < nlim) {
                    uint32_t pA[4];
                    #pragma unroll
                    for (int q2 = 0; q2 < 2; q2++) {
                        const float* sp = s[2*j + q2];
                        pA[q2*2 + 0] = pack_f2(sp[0], sp[1]);
                        pA[q2*2 + 1] = pack_f2(sp[2], sp[3]);
                    }
                    #pragma unroll
                    for (int nt = 0; nt < 4; nt++) {
                        uint32_t vh[4];
                        ldm_x4_t(smem_u32(Vh + (j * 16 + lrow) * LDH + nt * 16 + lh8), vh);
                        mma_f16(o[2*nt+0], pA, vh[0], vh[1]);
                        mma_f16(o[2*nt+1], pA, vh[2], vh[3]);
                    }
                }
            }
        }
    }

    // ---- epilogue: normalize, round, write fp16 attn ----
    #pragma unroll
    for (int hh = 0; hh < 2; hh++) {
        float inv = 1.0f / lsum[hh];
        int row = warp_row_lo + (lane >> 2) + hh * 8;
        size_t base = (size_t)(b * Sc + row) * Ec + h * HDc;
        #pragma unroll
        for (int n8 = 0; n8 < 8; n8++) {
            int d = n8 * 8 + (lane & 3) * 2;
            *reinterpret_cast<uint32_t*>(g_attn16 + base + d) =
                pack_f2(o[n8][2*hh] * inv, o[n8][2*hh+1] * inv);
        }
    }
}

// ===========================================================================
extern "C" void kernel_launch(void* const* d_in, const int* in_sizes, int n_in,
                              void* d_out, int out_size)
{
    const float* x      = (const float*)d_in[0];
    const float* qkv_w  = (const float*)d_in[1];
    const float* qkv_b  = (const float*)d_in[2];
    const float* out_w  = (const float*)d_in[3];
    const float* out_b  = (const float*)d_in[4];
    float* out = (float*)d_out;

    __half *x16, *wq16, *wo16, *qkv16, *a16;
    cudaGetSymbolAddress((void**)&x16,   g_x16);
    cudaGetSymbolAddress((void**)&wq16,  g_wq16);
    cudaGetSymbolAddress((void**)&wo16,  g_wo16);
    cudaGetSymbolAddress((void**)&qkv16, g_qkv16);
    cudaGetSymbolAddress((void**)&a16,   g_attn16);

    cudaFuncSetAttribute(gemm_f16_kernel<true>,
                         cudaFuncAttributeMaxDynamicSharedMemorySize, GEMM_SMEM);
    cudaFuncSetAttribute(gemm_f16_kernel<false>,
                         cudaFuncAttributeMaxDynamicSharedMemorySize, GEMM_SMEM);
    cudaFuncSetAttribute(flash_tc_kernel,
                         cudaFuncAttributeMaxDynamicSharedMemorySize, FLASH_SMEM);

    // 0) prepass
    round_all_kernel<<<(NALL4 + 255) / 256, 256>>>(x, qkv_w, out_w, x16, wq16, wo16);

    // 1) QKV projection -> fp16 qkv (q columns pre-scaled)
    dim3 g1(E3 / 128, Mc / 128);   // (24, 32)
    gemm_f16_kernel<true><<<g1, 256, GEMM_SMEM>>>(x16, wq16, qkv_b, nullptr, qkv16, Mc, E3, Ec);

    // 2) Flash attention -> fp16 attn (128-row q-tiles, 256 threads, 2 CTA/SM)
    dim3 g2(Sc / 128, Hc, Bc);     // (16, 16, 2)
    flash_tc_kernel<<<g2, 256, FLASH_SMEM>>>(qkv16);

    // 3) Output projection -> fp32 out
    dim3 g3(Ec / 128, Mc / 128);   // (8, 32)
    gemm_f16_kernel<false><<<g3, 256, GEMM_SMEM>>>(a16, wo16, out_b, out, nullptr, Mc, Ec, Ec);
}

// round 17
// speedup vs baseline: 1.0590x; 1.0028x over previous
#include <cuda_runtime.h>
#include <cuda_fp16.h>
#include <cstdint>
#include <math.h>

// ===========================================================================
// Problem constants
// ===========================================================================
constexpr int Bc = 2;
constexpr int Sc = 2048;
constexpr int Ec = 1024;
constexpr int Hc = 16;
constexpr int HDc = 64;
constexpr int Mc = Bc * Sc;        // 4096
constexpr int E3 = 3 * Ec;         // 3072

// Scratch (no cudaMalloc allowed)
__device__ __half g_x16[Mc * Ec];
__device__ __half g_wq16[E3 * Ec];
__device__ __half g_wo16[Ec * Ec];
__device__ __half g_qkv16[Mc * E3];
__device__ __half g_attn16[Mc * Ec];

// scores computed in log2 domain; scale folded into Q at QKV epilogue
constexpr float SCALE_LOG2E = 0.125f * 1.4426950408889634f;

// ===========================================================================
// Helpers
// ===========================================================================
__device__ __forceinline__ uint32_t pack_f2(float a, float b) {
    __half2 t = __float22half2_rn(make_float2(a, b));
    return *reinterpret_cast<uint32_t*>(&t);
}
__device__ __forceinline__ uint32_t smem_u32(const void* p) {
    return (uint32_t)__cvta_generic_to_shared(p);
}
__device__ __forceinline__ void ldm_x4(uint32_t addr, uint32_t r[4]) {
    asm volatile("ldmatrix.sync.aligned.m8n8.x4.shared.b16 {%0,%1,%2,%3}, [%4];"
        : "=r"(r[0]), "=r"(r[1]), "=r"(r[2]), "=r"(r[3]) : "r"(addr));
}
__device__ __forceinline__ void ldm_x4_t(uint32_t addr, uint32_t r[4]) {
    asm volatile("ldmatrix.sync.aligned.m8n8.x4.trans.shared.b16 {%0,%1,%2,%3}, [%4];"
        : "=r"(r[0]), "=r"(r[1]), "=r"(r[2]), "=r"(r[3]) : "r"(addr));
}
__device__ __forceinline__ void mma_f16(float c[4], const uint32_t a[4],
                                        uint32_t b0, uint32_t b1) {
    asm volatile(
        "mma.sync.aligned.m16n8k16.row.col.f32.f16.f16.f32 "
        "{%0,%1,%2,%3}, {%4,%5,%6,%7}, {%8,%9}, {%0,%1,%2,%3};"
        : "+f"(c[0]), "+f"(c[1]), "+f"(c[2]), "+f"(c[3])
        : "r"(a[0]), "r"(a[1]), "r"(a[2]), "r"(a[3]), "r"(b0), "r"(b1));
}
#define CP16(dst, src) \
    asm volatile("cp.async.cg.shared.global [%0], [%1], 16;" :: "r"(dst), "l"(src))
#define CP_COMMIT() asm volatile("cp.async.commit_group;")
#define CP_WAIT0()  asm volatile("cp.async.wait_group 0;")
#define CP_WAIT1()  asm volatile("cp.async.wait_group 1;")

// ===========================================================================
// Prepass: round x, qkv_w, out_w fp32 -> fp16 in ONE kernel (grid-stride)
// ===========================================================================
constexpr int NX4  = Mc * Ec / 4;
constexpr int NWQ4 = E3 * Ec / 4;
constexpr int NWO4 = Ec * Ec / 4;
constexpr int NALL4 = NX4 + NWQ4 + NWO4;

__global__ __launch_bounds__(512)
void round_all_kernel(const float* __restrict__ x,
                      const float* __restrict__ wq,
                      const float* __restrict__ wo,
                      __half* __restrict__ x16,
                      __half* __restrict__ wq16,
                      __half* __restrict__ wo16)
{
    int stride = gridDim.x * blockDim.x;
    for (int i = blockIdx.x * blockDim.x + threadIdx.x; i < NALL4; i += stride) {
        const float* src; __half* dst; int j;
        if (i < NX4)             { src = x;  dst = x16;  j = i; }
        else if (i < NX4 + NWQ4) { src = wq; dst = wq16; j = i - NX4; }
        else                     { src = wo; dst = wo16; j = i - NX4 - NWQ4; }
        float4 v = reinterpret_cast<const float4*>(src)[j];
        reinterpret_cast<uint2*>(dst)[j] = make_uint2(pack_f2(v.x, v.y), pack_f2(v.z, v.w));
    }
}

// ===========================================================================
// fp16 GEMM: CTA 128x128, 8 warps (2M x 4N), warp tile 64x32.
// K-chunk 64, 3-stage cp.async pipeline, LDT=72 (conflict-free).
// HALF_OUT: fp16 C; q columns (col < Ec) pre-scaled by SCALE_LOG2E.
// ===========================================================================
constexpr int LDT = 72;
constexpr int TEL = 128 * LDT;               // 9216 elems per tile
constexpr int STAGE = 2 * TEL;               // A+B = 18432 elems
constexpr int GEMM_SMEM = 3 * STAGE * 2;     // 110592 B

template<bool HALF_OUT>
__global__ __launch_bounds__(256, 2)
void gemm_f16_kernel(const __half* __restrict__ Ag, const __half* __restrict__ Bg,
                     const float* __restrict__ bias,
                     float* __restrict__ C, __half* __restrict__ Ch,
                     int M, int N, int K)
{
    extern __shared__ __half sm[];

    int tid  = threadIdx.x;
    int lane = tid & 31;
    int wid  = tid >> 5;
    int wm   = wid >> 2;
    int wn   = wid & 3;
    int bm   = blockIdx.y * 128;
    int bn   = blockIdx.x * 128;

    int lrow  = lane & 15;
    int lhalf = (lane >> 4) * 8;

    int r0  = tid >> 2;            // 0..63
    int seg = (tid & 3) * 16;      // 0,16,32,48 (halves)

    const __half* gsA = Ag + (size_t)bm * K;
    const __half* gsB = Bg + (size_t)bn * K;

    auto load_stage = [&](int stg, int k0) {
        __half* st = sm + stg * STAGE;
        #pragma unroll
        for (int i = 0; i < 2; i++) {
            int row = r0 + 64 * i;
            const __half* ga = gsA + (size_t)row * K + k0 + seg;
            const __half* gb = gsB + (size_t)row * K + k0 + seg;
            uint32_t sa = smem_u32(st + row * LDT + seg);
            uint32_t sb = smem_u32(st + TEL + row * LDT + seg);
            CP16(sa,      ga);
            CP16(sa + 16, ga + 8);
            CP16(sb,      gb);
            CP16(sb + 16, gb + 8);
        }
    };

    float acc[4][4][4] = {};

    load_stage(0, 0);  CP_COMMIT();
    load_stage(1, 64); CP_COMMIT();

    const int nch = K / 64;   // 16
    int slot = 0;
    for (int c = 0; c < nch; c++) {
        CP_WAIT1();
        __syncthreads();

        if (c + 2 < nch) load_stage((c + 2) % 3, (c + 2) * 64);
        CP_COMMIT();

        __half* A = sm + slot * STAGE;
        __half* B = A + TEL;
        slot = (slot == 2) ? 0 : slot + 1;

        #pragma unroll
        for (int ks = 0; ks < 4; ks++) {
            int kk = ks * 16 + lhalf;

            uint32_t af[4][4];
            uint32_t bf[2][4];
            #pragma unroll
            for (int mt = 0; mt < 4; mt++)
                ldm_x4(smem_u32(A + (wm * 64 + mt * 16 + lrow) * LDT + kk), af[mt]);
            #pragma unroll
            for (int nt = 0; nt < 2; nt++)
                ldm_x4(smem_u32(B + (wn * 32 + nt * 16 + lrow) * LDT + kk), bf[nt]);

            #pragma unroll
            for (int mt = 0; mt < 4; mt++)
                #pragma unroll
                for (int nt = 0; nt < 2; nt++) {
                    mma_f16(acc[mt][nt*2+0], af[mt], bf[nt][0], bf[nt][2]);
                    mma_f16(acc[mt][nt*2+1], af[mt], bf[nt][1], bf[nt][3]);
                }
        }
    }

    // ---- epilogue ----
    #pragma unroll
    for (int mt = 0; mt < 4; mt++) {
        int row = bm + wm * 64 + mt * 16 + (lane >> 2);
        #pragma unroll
        for (int n8 = 0; n8 < 4; n8++) {
            int col = bn + wn * 32 + n8 * 8 + (lane & 3) * 2;
            float2 bb = *reinterpret_cast<const float2*>(bias + col);
            float v0 = acc[mt][n8][0] + bb.x, v1 = acc[mt][n8][1] + bb.y;
            float v2 = acc[mt][n8][2] + bb.x, v3 = acc[mt][n8][3] + bb.y;
            if (HALF_OUT) {
                float qs = (col < Ec) ? SCALE_LOG2E : 1.0f;
                v0 *= qs; v1 *= qs; v2 *= qs; v3 *= qs;
                *reinterpret_cast<uint32_t*>(Ch + (size_t)row * N + col)       = pack_f2(v0, v1);
                *reinterpret_cast<uint32_t*>(Ch + (size_t)(row + 8) * N + col) = pack_f2(v2, v3);
            } else {
                *reinterpret_cast<float2*>(C + (size_t)row * N + col)       = make_float2(v0, v1);
                *reinterpret_cast<float2*>(C + (size_t)(row + 8) * N + col) = make_float2(v2, v3);
            }
        }
    }
}

// ===========================================================================
// Flash attention (causal), tensor cores, plain fp16. Best (R14) config:
// 128 q-rows, 256 threads (8 warps x 16 rows), 2 CTAs/SM, 3-stage KV pipeline.
// Q pre-scaled (log2 domain); fine-grained causal skip (exact).
// ===========================================================================
constexpr int LDH = 72;
constexpr int FQ  = 128 * LDH;               // 9216
constexpr int FKV = 64 * LDH;                // 4608
constexpr int KVSTAGE = 2 * FKV;             // Kh, Vh = 9216
constexpr int FLASH_ELEMS = FQ + 3 * KVSTAGE;       // 36864
constexpr int FLASH_SMEM  = FLASH_ELEMS * 2;        // 73728 B

__global__ __launch_bounds__(256, 2)
void flash_tc_kernel(const __half* __restrict__ qkv)
{
    extern __shared__ __half fs[];
    __half* Qh = fs;
    __half* KV = fs + FQ;

    int tid  = threadIdx.x;
    int lane = tid & 31;
    int wq   = tid >> 5;
    int qt   = gridDim.x - 1 - blockIdx.x;    // heavy q-tiles first
    int h    = blockIdx.y;
    int b    = blockIdx.z;
    int q0   = qt * 128;

    int lrow = lane & 15;
    int lh8  = (lane >> 4) * 8;
    int warp_row_lo = q0 + wq * 16;

    {
        #pragma unroll
        for (int i = 0; i < 4; i++) {
            int s   = tid + 256 * i;
            int row = s >> 3;
            int ch  = (s & 7) * 8;
            CP16(smem_u32(Qh + row * LDH + ch),
                 qkv + (size_t)(b * Sc + q0 + row) * E3 + h * HDc + ch);
        }
    }

    auto load_kv = [&](int stg, int kc0) {
        __half* st = KV + stg * KVSTAGE;
        #pragma unroll
        for (int i = 0; i < 2; i++) {
            int s   = tid + 256 * i;
            int row = s >> 3;
            int ch  = (s & 7) * 8;
            size_t gk = (size_t)(b * Sc + kc0 + row) * E3 + Ec + h * HDc + ch;
            uint32_t so = row * LDH + ch;
            CP16(smem_u32(st + so),       qkv + gk);
            CP16(smem_u32(st + FKV + so), qkv + gk + Ec);
        }
    };

    const int nkt = 2 * qt + 2;
    load_kv(0, 0);  CP_COMMIT();   // group: Q + KV0
    load_kv(1, 64); CP_COMMIT();

    float o[8][4] = {};
    float mrow[2] = {-1e30f, -1e30f};
    float lsum[2] = {0.f, 0.f};

    uint32_t aqf[4][4];
    bool qloaded = false;

    int slot = 0;
    for (int kt = 0; kt < nkt; kt++) {
        int kc0 = kt * 64;
        CP_WAIT1();
        __syncthreads();

        if (kt + 2 < nkt) load_kv((kt + 2) % 3, (kt + 2) * 64);
        CP_COMMIT();

        __half* Kh = KV + slot * KVSTAGE;
        __half* Vh = Kh + FKV;
        slot = (slot == 2) ? 0 : slot + 1;

        if (kc0 <= warp_row_lo + 15) {
            if (!qloaded) {
                #pragma unroll
                for (int ksj = 0; ksj < 4; ksj++)
                    ldm_x4(smem_u32(Qh + (wq * 16 + lrow) * LDH + ksj * 16 + lh8), aqf[ksj]);
                qloaded = true;
            }
            bool domask = (kc0 + 63 > warp_row_lo);
            int dnt  = (warp_row_lo - kc0) >> 4;
            int nlim = domask ? dnt + 1 : 4;

            // ---- S = Q K^T (1-pass; skip fully-masked subtiles) ----
            float s[8][4] = {};
            #pragma unroll
            for (int ksj = 0; ksj < 4; ksj++) {
                int kk = ksj * 16 + lh8;
                #pragma unroll
                for (int nt = 0; nt < 4; nt++) {
                    if (nt < nlim) {
                        uint32_t kh[4];
                        ldm_x4(smem_u32(Kh + (nt * 16 + lrow) * LDH + kk), kh);
                        mma_f16(s[2*nt+0], aqf[ksj], kh[0], kh[2]);
                        mma_f16(s[2*nt+1], aqf[ksj], kh[1], kh[3]);
                    }
                }
            }

            // ---- mask (scale already folded into Q) ----
            if (domask) {
                int r_lo = warp_row_lo + (lane >> 2);
                #pragma unroll
                for (int n8 = 0; n8 < 8; n8++) {
                    #pragma unroll
                    for (int cc = 0; cc < 4; cc++) {
                        float v = s[n8][cc];
                        if ((n8 >> 1) > dnt) {
                            v = -1e30f;
                        } else if ((n8 >> 1) == dnt) {
                            int col = kc0 + n8 * 8 + (lane & 3) * 2 + (cc & 1);
                            int row = r_lo + (cc >> 1) * 8;
                            if (col > row) v = -1e30f;
                        }
                        s[n8][cc] = v;
                    }
                }
            }

            // ---- online softmax (exp2 domain) ----
            #pragma unroll
            for (int hh = 0; hh < 2; hh++) {
                float tm = -1e30f;
                #pragma unroll
                for (int n8 = 0; n8 < 8; n8++)
                    tm = fmaxf(tm, fmaxf(s[n8][2*hh], s[n8][2*hh+1]));
                tm = fmaxf(tm, __shfl_xor_sync(0xffffffffu, tm, 1));
                tm = fmaxf(tm, __shfl_xor_sync(0xffffffffu, tm, 2));
                float mn = fmaxf(mrow[hh], tm);
                float corr = exp2f(mrow[hh] - mn);
                mrow[hh] = mn;
                float rs = 0.f;
                #pragma unroll
                for (int n8 = 0; n8 < 8; n8++) {
                    s[n8][2*hh]   = exp2f(s[n8][2*hh]   - mn);
                    s[n8][2*hh+1] = exp2f(s[n8][2*hh+1] - mn);
                    rs += s[n8][2*hh] + s[n8][2*hh+1];
                }
                rs += __shfl_xor_sync(0xffffffffu, rs, 1);
                rs += __shfl_xor_sync(0xffffffffu, rs, 2);
                lsum[hh] = lsum[hh] * corr + rs;
                #pragma unroll
                for (int n8 = 0; n8 < 8; n8++) {
                    o[n8][2*hh]   *= corr;
                    o[n8][2*hh+1] *= corr;
                }
            }

            // ---- O += P V (1-pass; skip zero key-subtiles — exact) ----
            #pragma unroll
            for (int j = 0; j < 4; j++) {
                if (j < nlim) {
                    uint32_t pA[4];
                    #pragma unroll
                    for (int q2 = 0; q2 < 2; q2++) {
                        const float* sp = s[2*j + q2];
                        pA[q2*2 + 0] = pack_f2(sp[0], sp[1]);
                        pA[q2*2 + 1] = pack_f2(sp[2], sp[3]);
                    }
                    #pragma unroll
                    for (int nt = 0; nt < 4; nt++) {
                        uint32_t vh[4];
                        ldm_x4_t(smem_u32(Vh + (j * 16 + lrow) * LDH + nt * 16 + lh8), vh);
                        mma_f16(o[2*nt+0], pA, vh[0], vh[1]);
                        mma_f16(o[2*nt+1], pA, vh[2], vh[3]);
                    }
                }
            }
        }
    }

    // ---- epilogue: normalize, round, write fp16 attn ----
    #pragma unroll
    for (int hh = 0; hh < 2; hh++) {
        float inv = 1.0f / lsum[hh];
        int row = warp_row_lo + (lane >> 2) + hh * 8;
        size_t base = (size_t)(b * Sc + row) * Ec + h * HDc;
        #pragma unroll
        for (int n8 = 0; n8 < 8; n8++) {
            int d = n8 * 8 + (lane & 3) * 2;
            *reinterpret_cast<uint32_t*>(g_attn16 + base + d) =
                pack_f2(o[n8][2*hh] * inv, o[n8][2*hh+1] * inv);
        }
    }
}

// ===========================================================================
extern "C" void kernel_launch(void* const* d_in, const int* in_sizes, int n_in,
                              void* d_out, int out_size)
{
    const float* x      = (const float*)d_in[0];
    const float* qkv_w  = (const float*)d_in[1];
    const float* qkv_b  = (const float*)d_in[2];
    const float* out_w  = (const float*)d_in[3];
    const float* out_b  = (const float*)d_in[4];
    float* out = (float*)d_out;

    __half *x16, *wq16, *wo16, *qkv16, *a16;
    cudaGetSymbolAddress((void**)&x16,   g_x16);
    cudaGetSymbolAddress((void**)&wq16,  g_wq16);
    cudaGetSymbolAddress((void**)&wo16,  g_wo16);
    cudaGetSymbolAddress((void**)&qkv16, g_qkv16);
    cudaGetSymbolAddress((void**)&a16,   g_attn16);

    cudaFuncSetAttribute(gemm_f16_kernel<true>,
                         cudaFuncAttributeMaxDynamicSharedMemorySize, GEMM_SMEM);
    cudaFuncSetAttribute(gemm_f16_kernel<false>,
                         cudaFuncAttributeMaxDynamicSharedMemorySize, GEMM_SMEM);
    cudaFuncSetAttribute(flash_tc_kernel,
                         cudaFuncAttributeMaxDynamicSharedMemorySize, FLASH_SMEM);

    // 0) prepass (grid-stride, 512-thread blocks; ~4 waves of full chip)
    round_all_kernel<<<1184, 512>>>(x, qkv_w, out_w, x16, wq16, wo16);

    // 1) QKV projection -> fp16 qkv (q columns pre-scaled)
    dim3 g1(E3 / 128, Mc / 128);   // (24, 32)
    gemm_f16_kernel<true><<<g1, 256, GEMM_SMEM>>>(x16, wq16, qkv_b, nullptr, qkv16, Mc, E3, Ec);

    // 2) Flash attention -> fp16 attn (128-row q-tiles, 256 threads, 2 CTA/SM)
    dim3 g2(Sc / 128, Hc, Bc);     // (16, 16, 2)
    flash_tc_kernel<<<g2, 256, FLASH_SMEM>>>(qkv16);

    // 3) Output projection -> fp32 out
    dim3 g3(Ec / 128, Mc / 128);   // (8, 32)
    gemm_f16_kernel<false><<<g3, 256, GEMM_SMEM>>>(a16, wo16, out_b, out, nullptr, Mc, Ec, Ec);
}